// round 2
// baseline (speedup 1.0000x reference)
#include <cuda_runtime.h>
#include <math_constants.h>

#define NN   768
#define IN   68
#define KNB  8
#define EO   32
#define FEAT 264      // IN*2 + EO*4
#define XW   132      // per-node feature width: IN + EO + EO
#define EMB  32
#define MPAIR 294528  // N*(N-1)/2
#define EPS  1e-5f

// ---------------- scratch (device globals, no allocation) ----------------
__device__ int   g_idx[2][NN][KNB];
__device__ float g_e1[2][NN][EO];
__device__ float g_x[2][NN][XW];
__device__ float g_scale[FEAT];
__device__ float g_shift[FEAT];
__device__ float g_A[2][NN][EMB];
__device__ float g_B[2][NN][EMB];

__device__ __forceinline__ float lrelu(float x) { return fmaxf(x, 0.01f * x); }

// ---------------- 1) KNN: one warp per node ----------------
__global__ void knn_kernel(const float* __restrict__ feat0,
                           const float* __restrict__ feat1) {
    int g    = blockIdx.y;
    int node = blockIdx.x;
    int lane = threadIdx.x;
    const float* feat = g ? feat1 : feat0;

    float4 ci = *(const float4*)(feat + node * IN);
    float dloc[NN / 32];
#pragma unroll
    for (int t = 0; t < NN / 32; t++) {
        int j = lane + t * 32;
        float4 cj = *(const float4*)(feat + j * IN);
        dloc[t] = fabsf(ci.x - cj.x) + fabsf(ci.y - cj.y) +
                  fabsf(ci.z - cj.z) + fabsf(ci.w - cj.w);
    }
    // 8 rounds of warp-wide argmin, ties -> lowest index (matches top_k stability)
    for (int r = 0; r < KNB; r++) {
        float best = CUDART_INF_F;
        int bt = -1;
#pragma unroll
        for (int t = 0; t < NN / 32; t++)
            if (dloc[t] < best) { best = dloc[t]; bt = t; }
        int bj = lane + bt * 32;   // bogus if bt==-1, but key won't win then
        unsigned long long key =
            (((unsigned long long)__float_as_uint(best)) << 32) | (unsigned)bj;
#pragma unroll
        for (int off = 16; off; off >>= 1) {
            unsigned long long other = __shfl_xor_sync(0xffffffffu, key, off);
            if (other < key) key = other;
        }
        int wj = (int)(key & 0xffffffffu);
        if (lane == (wj & 31)) dloc[wj >> 5] = CUDART_INF_F;
        if (lane == 0) g_idx[g][node][r] = wj;
    }
}

// ---------------- 2) EdgeConv1: one 32-thread block per node ----------------
__global__ void ec1_kernel(const float* __restrict__ feat0,
                           const float* __restrict__ feat1,
                           const float* __restrict__ w1, const float* __restrict__ b1,
                           const float* __restrict__ w2, const float* __restrict__ b2) {
    __shared__ float sh[KNB][IN];
    __shared__ float s1[EO];
    int g = blockIdx.y, node = blockIdx.x, o = threadIdx.x;
    const float* feat = g ? feat1 : feat0;

    for (int t = o; t < KNB * IN; t += 32) {
        int k = t / IN, f = t % IN;
        sh[k][f] = feat[g_idx[g][node][k] * IN + f];
    }
    __syncthreads();

    float pre = b1[o];
    for (int f = 0; f < IN; f++) {
#pragma unroll
        for (int k = 0; k < KNB; k++)
            pre += sh[k][f] * w1[(f * KNB + k) * EO + o];
    }
    s1[o] = lrelu(pre);
    __syncthreads();

    float h = b2[o];
#pragma unroll
    for (int k = 0; k < EO; k++) h += s1[k] * w2[k * EO + o];
    g_e1[g][node][o] = lrelu(h);
}

// ---------------- 3) EdgeConv2 + assemble x = [feat|e1|e2] ----------------
__global__ void ec2_kernel(const float* __restrict__ feat0,
                           const float* __restrict__ feat1,
                           const float* __restrict__ w1, const float* __restrict__ b1,
                           const float* __restrict__ w2, const float* __restrict__ b2) {
    __shared__ float sh[KNB][EO];
    __shared__ float s1[EO];
    int g = blockIdx.y, node = blockIdx.x, o = threadIdx.x;

    for (int t = o; t < KNB * EO; t += 32) {
        int k = t / EO, f = t % EO;
        sh[k][f] = g_e1[g][g_idx[g][node][k]][f];
    }
    __syncthreads();

    float pre = b1[o];
    for (int f = 0; f < EO; f++) {
#pragma unroll
        for (int k = 0; k < KNB; k++)
            pre += sh[k][f] * w1[(f * KNB + k) * EO + o];
    }
    s1[o] = lrelu(pre);
    __syncthreads();

    float h = b2[o];
#pragma unroll
    for (int k = 0; k < EO; k++) h += s1[k] * w2[k * EO + o];
    float e2 = lrelu(h);

    const float* feat = g ? feat1 : feat0;
    float* xp = g_x[g][node];
    for (int f = o; f < IN; f += 32) xp[f] = feat[node * IN + f];
    xp[IN + o]      = g_e1[g][node][o];
    xp[IN + EO + o] = e2;
}

// ---------------- 4) BN statistics via weighted node sums ----------------
__global__ void bn_kernel(const float* __restrict__ bn_g,
                          const float* __restrict__ bn_b) {
    int f = blockIdx.x;       // 0..131
    int tid = threadIdx.x;    // 256
    double s1 = 0, s2 = 0, q1 = 0, q2 = 0;
    for (int t = tid; t < 2 * NN; t += 256) {
        int g = t / NN, i = t % NN;
        double v  = (double)g_x[g][i][f];
        double wa = (double)(NN - 1 - i);   // occurrences as pair-element i (first half)
        double wb = (double)i;              // occurrences as pair-element j (second half)
        s1 += wa * v; s2 += wb * v;
        q1 += wa * v * v; q2 += wb * v * v;
    }
    __shared__ double red[4][256];
    red[0][tid] = s1; red[1][tid] = s2; red[2][tid] = q1; red[3][tid] = q2;
    __syncthreads();
    for (int s = 128; s; s >>= 1) {
        if (tid < s)
#pragma unroll
            for (int c = 0; c < 4; c++) red[c][tid] += red[c][tid + s];
        __syncthreads();
    }
    if (tid == 0) {
        double cnt = 2.0 * (double)MPAIR;
        double mu1 = red[0][0] / cnt, var1 = red[2][0] / cnt - mu1 * mu1;
        double mu2 = red[1][0] / cnt, var2 = red[3][0] / cnt - mu2 * mu2;
        float sc1 = bn_g[f]        * rsqrtf((float)var1 + EPS);
        float sc2 = bn_g[XW + f]   * rsqrtf((float)var2 + EPS);
        g_scale[f]      = sc1;
        g_scale[XW + f] = sc2;
        g_shift[f]      = bn_b[f]      - (float)mu1 * sc1;
        g_shift[XW + f] = bn_b[XW + f] - (float)mu2 * sc2;
    }
}

// ---------------- 5) per-node A, B (lin1 split + BN folded) ----------------
__global__ void ab_kernel(const float* __restrict__ lin1_w,
                          const float* __restrict__ lin1_b) {
    int g = blockIdx.y, node = blockIdx.x, o = threadIdx.x;
    // effective bias: lin1_b + sum_ff shift[ff]*W1[ff][o] (folded into A)
    float be = lin1_b[o];
    for (int ff = 0; ff < FEAT; ff++) be += g_shift[ff] * lin1_w[ff * EMB + o];

    const float* x = g_x[g][node];
    float a = be, b = 0.f;
    for (int f = 0; f < XW; f++) {
        float xv = x[f];
        a += xv * g_scale[f]      * lin1_w[f * EMB + o];
        b += xv * g_scale[XW + f] * lin1_w[(XW + f) * EMB + o];
    }
    g_A[g][node][o] = a;
    g_B[g][node][o] = b;
}

// ---------------- 6) main pair kernel ----------------
__global__ void __launch_bounds__(256) pair_kernel(
        const float* __restrict__ w2, const float* __restrict__ b2,
        const float* __restrict__ w3, const float* __restrict__ b3,
        float* __restrict__ out) {
    __shared__ float W2t[EMB][EMB];   // W2t[n][k] = w2[k][n]
    __shared__ float W3s[EMB][2];
    __shared__ float b2s[EMB];
    __shared__ float b3s[2];
    int tid = threadIdx.x;
    for (int t = tid; t < EMB * EMB; t += 256) W2t[t % EMB][t / EMB] = w2[t];
    for (int t = tid; t < EMB * 2; t += 256)  W3s[t / 2][t % 2] = w3[t];
    if (tid < EMB) b2s[tid] = b2[tid];
    if (tid < 2)   b3s[tid] = b3[tid];
    __syncthreads();

    int g = blockIdx.y;
    int q = blockIdx.x * 256 + tid;
    if (q >= MPAIR) return;

    // decode (i, j): largest i with L(i)=i*(2N-1-i)/2 <= q
    int lo = 0, hi = NN - 2;
    while (lo < hi) {
        int mid = (lo + hi + 1) >> 1;
        if (mid * (2 * NN - 1 - mid) / 2 <= q) lo = mid; else hi = mid - 1;
    }
    int i = lo;
    int j = i + 1 + (q - i * (2 * NN - 1 - i) / 2);

    const float4* Ap = (const float4*)g_A[g][i];
    const float4* Bp = (const float4*)g_B[g][j];
    float h1[EMB];
#pragma unroll
    for (int t = 0; t < 8; t++) {
        float4 a = Ap[t], b = Bp[t];
        h1[4 * t + 0] = lrelu(a.x + b.x);
        h1[4 * t + 1] = lrelu(a.y + b.y);
        h1[4 * t + 2] = lrelu(a.z + b.z);
        h1[4 * t + 3] = lrelu(a.w + b.w);
    }

    float o0 = b3s[0], o1 = b3s[1];
#pragma unroll
    for (int n = 0; n < EMB; n++) {
        float s = b2s[n];
        const float4* wr = (const float4*)W2t[n];
#pragma unroll
        for (int t = 0; t < 8; t++) {
            float4 w = wr[t];
            s += h1[4 * t + 0] * w.x;
            s += h1[4 * t + 1] * w.y;
            s += h1[4 * t + 2] * w.z;
            s += h1[4 * t + 3] * w.w;
        }
        float h2 = lrelu(s);
        o0 += h2 * W3s[n][0];
        o1 += h2 * W3s[n][1];
    }
    long long row = (long long)g * MPAIR + q;
    ((float2*)out)[row] = make_float2(o0, o1);
}

// ---------------- launch ----------------
extern "C" void kernel_launch(void* const* d_in, const int* in_sizes, int n_in,
                              void* d_out, int out_size) {
    const float* feat0  = (const float*)d_in[0];
    const float* feat1  = (const float*)d_in[1];
    const float* ec1_w1 = (const float*)d_in[2];
    const float* ec1_b1 = (const float*)d_in[3];
    const float* ec1_w2 = (const float*)d_in[4];
    const float* ec1_b2 = (const float*)d_in[5];
    const float* ec2_w1 = (const float*)d_in[6];
    const float* ec2_b1 = (const float*)d_in[7];
    const float* ec2_w2 = (const float*)d_in[8];
    const float* ec2_b2 = (const float*)d_in[9];
    const float* bn_g   = (const float*)d_in[10];
    const float* bn_b   = (const float*)d_in[11];
    const float* lin1_w = (const float*)d_in[12];
    const float* lin1_b = (const float*)d_in[13];
    const float* lin2_w = (const float*)d_in[14];
    const float* lin2_b = (const float*)d_in[15];
    const float* lin3_w = (const float*)d_in[16];
    const float* lin3_b = (const float*)d_in[17];
    float* out = (float*)d_out;

    dim3 gNode(NN, 2);
    knn_kernel<<<gNode, 32>>>(feat0, feat1);
    ec1_kernel<<<gNode, 32>>>(feat0, feat1, ec1_w1, ec1_b1, ec1_w2, ec1_b2);
    ec2_kernel<<<gNode, 32>>>(feat0, feat1, ec2_w1, ec2_b1, ec2_w2, ec2_b2);
    bn_kernel<<<XW, 256>>>(bn_g, bn_b);
    ab_kernel<<<gNode, 32>>>(lin1_w, lin1_b);
    dim3 gPair((MPAIR + 255) / 256, 2);
    pair_kernel<<<gPair, 256>>>(lin2_w, lin2_b, lin3_w, lin3_b, out);
}

// round 7
// speedup vs baseline: 1.0180x; 1.0180x over previous
#include <cuda_runtime.h>
#include <math_constants.h>

#define NN   768
#define IN   68
#define KNB  8
#define EO   32
#define FEAT 264      // IN*2 + EO*4
#define XW   132      // per-node feature width: IN + EO + EO
#define EMB  32
#define MPAIR 294528  // N*(N-1)/2
#define EPS  1e-5f

// ---------------- scratch (device globals, no allocation) ----------------
__device__ int   g_idx[2][NN][KNB];
__device__ float g_e1[2][NN][EO];
__device__ float g_x[2][NN][XW];
__device__ float g_scale[FEAT];
__device__ float g_shift[FEAT];
__device__ __align__(16) float g_A[2][NN][EMB];
__device__ __align__(16) float g_B[2][NN][EMB];

__device__ __forceinline__ float lrelu(float x) { return fmaxf(x, 0.01f * x); }

// ---- packed f32x2 helpers (sm_103a) ----
__device__ __forceinline__ unsigned long long pk2(float lo, float hi) {
    unsigned long long r;
    asm("mov.b64 %0, {%1,%2};" : "=l"(r) : "f"(lo), "f"(hi));
    return r;
}
__device__ __forceinline__ void upk2(float& lo, float& hi, unsigned long long p) {
    asm("mov.b64 {%0,%1}, %2;" : "=f"(lo), "=f"(hi) : "l"(p));
}
__device__ __forceinline__ unsigned long long fma2(unsigned long long a,
                                                   unsigned long long b,
                                                   unsigned long long c) {
    unsigned long long d;
    asm("fma.rn.f32x2 %0, %1, %2, %3;" : "=l"(d) : "l"(a), "l"(b), "l"(c));
    return d;
}
__device__ __forceinline__ unsigned long long add2(unsigned long long a,
                                                   unsigned long long b) {
    unsigned long long d;
    asm("add.rn.f32x2 %0, %1, %2;" : "=l"(d) : "l"(a), "l"(b));
    return d;
}
__device__ __forceinline__ unsigned long long mul2(unsigned long long a,
                                                   unsigned long long b) {
    unsigned long long d;
    asm("mul.rn.f32x2 %0, %1, %2;" : "=l"(d) : "l"(a), "l"(b));
    return d;
}
// packed lrelu: 0.505*x + 0.495*|x|  (==x for x>=0, ~0.01x for x<0; err ~1e-7)
__device__ __forceinline__ unsigned long long lrelu2(unsigned long long x,
                                                     unsigned long long c1,
                                                     unsigned long long c2) {
    unsigned long long ax = x & 0x7FFFFFFF7FFFFFFFull;
    return fma2(x, c1, mul2(ax, c2));
}

// ---------------- 1) KNN: 8 warps/block, coords staged in shared ----------------
__global__ void __launch_bounds__(256) knn_kernel(const float* __restrict__ feat0,
                                                  const float* __restrict__ feat1) {
    __shared__ float4 sc[NN];   // 12 KB
    int g = blockIdx.y;
    int tid = threadIdx.x, wid = tid >> 5, lane = tid & 31;
    const float* feat = g ? feat1 : feat0;
    for (int t = tid; t < NN; t += 256)
        sc[t] = *(const float4*)(feat + t * IN);
    __syncthreads();

    int node = blockIdx.x * 8 + wid;
    float4 ci = sc[node];
    float dloc[NN / 32];
#pragma unroll
    for (int t = 0; t < NN / 32; t++) {
        float4 cj = sc[lane + t * 32];
        dloc[t] = fabsf(ci.x - cj.x) + fabsf(ci.y - cj.y) +
                  fabsf(ci.z - cj.z) + fabsf(ci.w - cj.w);
    }
    for (int r = 0; r < KNB; r++) {
        float best = CUDART_INF_F;
        int bt = 0;
#pragma unroll
        for (int t = 0; t < NN / 32; t++)
            if (dloc[t] < best) { best = dloc[t]; bt = t; }
        int bj = lane + bt * 32;
        unsigned long long key =
            (((unsigned long long)__float_as_uint(best)) << 32) | (unsigned)bj;
#pragma unroll
        for (int off = 16; off; off >>= 1) {
            unsigned long long other = __shfl_xor_sync(0xffffffffu, key, off);
            if (other < key) key = other;
        }
        int wj = (int)(key & 0xffffffffu);
        if (lane == (wj & 31)) dloc[wj >> 5] = CUDART_INF_F;
        if (lane == 0) g_idx[g][node][r] = wj;
    }
}

// ---------------- 2) EdgeConv1: 8 warps/block, 2 nodes per warp ----------------
__global__ void __launch_bounds__(256) ec1_kernel(
        const float* __restrict__ feat0, const float* __restrict__ feat1,
        const float* __restrict__ w1, const float* __restrict__ b1,
        const float* __restrict__ w2, const float* __restrict__ b2) {
    __shared__ float sh[16][KNB][IN];   // 34.8 KB
    __shared__ float s1[16][EO];
    int g = blockIdx.y;
    int wid = threadIdx.x >> 5, lane = threadIdx.x & 31;
    int n0 = blockIdx.x * 16 + wid * 2;
    const float* feat = g ? feat1 : feat0;

#pragma unroll
    for (int nn = 0; nn < 2; nn++) {
        int node = n0 + nn;
        for (int t = lane; t < KNB * IN; t += 32) {
            int k = t / IN, f = t - k * IN;
            sh[wid * 2 + nn][k][f] = feat[g_idx[g][node][k] * IN + f];
        }
    }
    __syncwarp();

    float pa = b1[lane], pb = pa;
    const float (*sa)[IN] = sh[wid * 2];
    const float (*sb)[IN] = sh[wid * 2 + 1];
    for (int f = 0; f < IN; f++) {
#pragma unroll
        for (int k = 0; k < KNB; k++) {
            float w = w1[(f * KNB + k) * EO + lane];
            pa = fmaf(sa[k][f], w, pa);
            pb = fmaf(sb[k][f], w, pb);
        }
    }
    s1[wid * 2][lane]     = lrelu(pa);
    s1[wid * 2 + 1][lane] = lrelu(pb);
    __syncwarp();

    float ha = b2[lane], hb = ha;
#pragma unroll
    for (int k = 0; k < EO; k++) {
        float w = w2[k * EO + lane];
        ha = fmaf(s1[wid * 2][k], w, ha);
        hb = fmaf(s1[wid * 2 + 1][k], w, hb);
    }
    g_e1[g][n0][lane]     = lrelu(ha);
    g_e1[g][n0 + 1][lane] = lrelu(hb);
}

// ---------------- 3) EdgeConv2 + assemble x = [feat|e1|e2] ----------------
__global__ void __launch_bounds__(256) ec2_kernel(
        const float* __restrict__ feat0, const float* __restrict__ feat1,
        const float* __restrict__ w1, const float* __restrict__ b1,
        const float* __restrict__ w2, const float* __restrict__ b2) {
    __shared__ float sh[16][KNB][EO];   // 16 KB
    __shared__ float s1[16][EO];
    int g = blockIdx.y;
    int wid = threadIdx.x >> 5, lane = threadIdx.x & 31;
    int n0 = blockIdx.x * 16 + wid * 2;

#pragma unroll
    for (int nn = 0; nn < 2; nn++) {
        int node = n0 + nn;
        for (int t = lane; t < KNB * EO; t += 32) {
            int k = t >> 5, f = t & 31;
            sh[wid * 2 + nn][k][f] = g_e1[g][g_idx[g][node][k]][f];
        }
    }
    __syncwarp();

    float pa = b1[lane], pb = pa;
    const float (*sa)[EO] = sh[wid * 2];
    const float (*sb)[EO] = sh[wid * 2 + 1];
    for (int f = 0; f < EO; f++) {
#pragma unroll
        for (int k = 0; k < KNB; k++) {
            float w = w1[(f * KNB + k) * EO + lane];
            pa = fmaf(sa[k][f], w, pa);
            pb = fmaf(sb[k][f], w, pb);
        }
    }
    s1[wid * 2][lane]     = lrelu(pa);
    s1[wid * 2 + 1][lane] = lrelu(pb);
    __syncwarp();

    float ha = b2[lane], hb = ha;
#pragma unroll
    for (int k = 0; k < EO; k++) {
        float w = w2[k * EO + lane];
        ha = fmaf(s1[wid * 2][k], w, ha);
        hb = fmaf(s1[wid * 2 + 1][k], w, hb);
    }
    const float* feat = g ? feat1 : feat0;
#pragma unroll
    for (int nn = 0; nn < 2; nn++) {
        int node = n0 + nn;
        float* xp = g_x[g][node];
        for (int f = lane; f < IN; f += 32) xp[f] = feat[node * IN + f];
        xp[IN + lane]      = g_e1[g][node][lane];
        xp[IN + EO + lane] = lrelu(nn == 0 ? ha : hb);
    }
}

// ---------------- 4) BN stats: warp per feature, fp32, shuffle reduce ----------------
__global__ void __launch_bounds__(128) bn_kernel(const float* __restrict__ bn_g,
                                                 const float* __restrict__ bn_b) {
    int warp = (blockIdx.x * 128 + threadIdx.x) >> 5;
    int lane = threadIdx.x & 31;
    if (warp >= XW) return;
    int f = warp;

    float s1 = 0.f, s2 = 0.f, q1 = 0.f, q2 = 0.f;
    for (int i = lane; i < NN; i += 32) {
        float wa = (float)(NN - 1 - i);
        float wb = (float)i;
#pragma unroll
        for (int g = 0; g < 2; g++) {
            float v = g_x[g][i][f];
            float wv = wa * v;
            s1 = fmaf(wa, v, s1);
            s2 = fmaf(wb, v, s2);
            q1 = fmaf(wv, v, q1);
            q2 = fmaf(wb * v, v, q2);
        }
    }
#pragma unroll
    for (int off = 16; off; off >>= 1) {
        s1 += __shfl_xor_sync(0xffffffffu, s1, off);
        s2 += __shfl_xor_sync(0xffffffffu, s2, off);
        q1 += __shfl_xor_sync(0xffffffffu, q1, off);
        q2 += __shfl_xor_sync(0xffffffffu, q2, off);
    }
    if (lane == 0) {
        float inv = 1.0f / (2.0f * (float)MPAIR);
        float mu1 = s1 * inv, var1 = fmaf(-mu1, mu1, q1 * inv);
        float mu2 = s2 * inv, var2 = fmaf(-mu2, mu2, q2 * inv);
        float sc1 = bn_g[f]      * rsqrtf(var1 + EPS);
        float sc2 = bn_g[XW + f] * rsqrtf(var2 + EPS);
        g_scale[f]      = sc1;
        g_scale[XW + f] = sc2;
        g_shift[f]      = bn_b[f]      - mu1 * sc1;
        g_shift[XW + f] = bn_b[XW + f] - mu2 * sc2;
    }
}

// ---------------- 5) per-node A, B (lin1 split + BN folded) ----------------
__global__ void __launch_bounds__(256) ab_kernel(const float* __restrict__ lin1_w,
                                                 const float* __restrict__ lin1_b) {
    int g = blockIdx.y;
    int wid = threadIdx.x >> 5, lane = threadIdx.x & 31;
    int node = blockIdx.x * 8 + wid;

    float be = lin1_b[lane];
    for (int ff = 0; ff < FEAT; ff++)
        be = fmaf(g_shift[ff], lin1_w[ff * EMB + lane], be);

    const float* x = g_x[g][node];
    float a = be, b = 0.f;
    for (int f = 0; f < XW; f++) {
        float xv = x[f];
        float sa = xv * g_scale[f];
        float sb = xv * g_scale[XW + f];
        a = fmaf(sa, lin1_w[f * EMB + lane], a);
        b = fmaf(sb, lin1_w[(XW + f) * EMB + lane], b);
    }
    g_A[g][node][lane] = a;
    g_B[g][node][lane] = b;
}

// ---------------- 6) main pair kernel (f32x2-packed GEMV) ----------------
__global__ void __launch_bounds__(256) pair_kernel(
        const float* __restrict__ w2, const float* __restrict__ b2,
        const float* __restrict__ w3, const float* __restrict__ b3,
        float* __restrict__ out) {
    __shared__ __align__(16) float W2t[EMB][EMB];   // W2t[n][k] = w2[k][n]
    __shared__ float W3s[EMB][2];
    __shared__ float b2s[EMB];
    __shared__ float b3s[2];
    int tid = threadIdx.x;
    for (int t = tid; t < EMB * EMB; t += 256) W2t[t % EMB][t / EMB] = w2[t];
    for (int t = tid; t < EMB * 2; t += 256)  W3s[t / 2][t % 2] = w3[t];
    if (tid < EMB) b2s[tid] = b2[tid];
    if (tid < 2)   b3s[tid] = b3[tid];
    __syncthreads();

    int g = blockIdx.y;
    int q = blockIdx.x * 256 + tid;
    if (q >= MPAIR) return;

    // closed-form decode of (i, j) from q (exact int arithmetic in fp32 + fixup)
    float tf = 2.0f * NN - 1.0f;                    // 1535
    float disc = fmaf(tf, tf, -8.0f * (float)q);    // exact integer <= 2^24
    int i = (int)((tf - sqrtf(disc)) * 0.5f);
    i = min(max(i, 0), NN - 2);
    while (i > 0 && i * (2 * NN - 1 - i) / 2 > q) i--;
    while (i < NN - 2 && (i + 1) * (2 * NN - 1 - (i + 1)) / 2 <= q) i++;
    int j = i + 1 + (q - i * (2 * NN - 1 - i) / 2);

    const unsigned long long c1 = pk2(0.505f, 0.505f);
    const unsigned long long c2 = pk2(0.495f, 0.495f);

    const ulonglong2* Ap = (const ulonglong2*)g_A[g][i];
    const ulonglong2* Bp = (const ulonglong2*)g_B[g][j];
    unsigned long long h1p[16];
#pragma unroll
    for (int t = 0; t < 8; t++) {
        ulonglong2 a = Ap[t], b = Bp[t];
        h1p[2 * t]     = lrelu2(add2(a.x, b.x), c1, c2);
        h1p[2 * t + 1] = lrelu2(add2(a.y, b.y), c1, c2);
    }

    float o0 = b3s[0], o1 = b3s[1];
#pragma unroll
    for (int n = 0; n < EMB; n++) {
        unsigned long long acc0 = pk2(b2s[n], 0.f);
        unsigned long long acc1 = 0;   // {+0.f, +0.f}
        const ulonglong2* wr = (const ulonglong2*)W2t[n];
#pragma unroll
        for (int t = 0; t < 8; t++) {
            ulonglong2 w = wr[t];
            acc0 = fma2(h1p[2 * t],     w.x, acc0);
            acc1 = fma2(h1p[2 * t + 1], w.y, acc1);
        }
        float lo, hi, lo1, hi1;
        upk2(lo, hi, acc0);
        upk2(lo1, hi1, acc1);
        float s = (lo + lo1) + (hi + hi1);
        float h2 = fmaxf(s, 0.01f * s);
        o0 = fmaf(h2, W3s[n][0], o0);
        o1 = fmaf(h2, W3s[n][1], o1);
    }
    ((float2*)out)[(long long)g * MPAIR + q] = make_float2(o0, o1);
}

// ---------------- launch ----------------
extern "C" void kernel_launch(void* const* d_in, const int* in_sizes, int n_in,
                              void* d_out, int out_size) {
    const float* feat0  = (const float*)d_in[0];
    const float* feat1  = (const float*)d_in[1];
    const float* ec1_w1 = (const float*)d_in[2];
    const float* ec1_b1 = (const float*)d_in[3];
    const float* ec1_w2 = (const float*)d_in[4];
    const float* ec1_b2 = (const float*)d_in[5];
    const float* ec2_w1 = (const float*)d_in[6];
    const float* ec2_b1 = (const float*)d_in[7];
    const float* ec2_w2 = (const float*)d_in[8];
    const float* ec2_b2 = (const float*)d_in[9];
    const float* bn_g   = (const float*)d_in[10];
    const float* bn_b   = (const float*)d_in[11];
    const float* lin1_w = (const float*)d_in[12];
    const float* lin1_b = (const float*)d_in[13];
    const float* lin2_w = (const float*)d_in[14];
    const float* lin2_b = (const float*)d_in[15];
    const float* lin3_w = (const float*)d_in[16];
    const float* lin3_b = (const float*)d_in[17];
    float* out = (float*)d_out;

    knn_kernel<<<dim3(NN / 8, 2), 256>>>(feat0, feat1);
    ec1_kernel<<<dim3(NN / 16, 2), 256>>>(feat0, feat1, ec1_w1, ec1_b1, ec1_w2, ec1_b2);
    ec2_kernel<<<dim3(NN / 16, 2), 256>>>(feat0, feat1, ec2_w1, ec2_b1, ec2_w2, ec2_b2);
    bn_kernel<<<(XW * 32 + 127) / 128, 128>>>(bn_g, bn_b);
    ab_kernel<<<dim3(NN / 8, 2), 256>>>(lin1_w, lin1_b);
    pair_kernel<<<dim3((MPAIR + 255) / 256, 2), 256>>>(lin2_w, lin2_b, lin3_w, lin3_b, out);
}

// round 8
// speedup vs baseline: 1.3895x; 1.3649x over previous
#include <cuda_runtime.h>
#include <math_constants.h>

#define NN   768
#define IN   68
#define KNB  8
#define EO   32
#define FEAT 264      // IN*2 + EO*4
#define XW   132      // per-node feature width: IN + EO + EO
#define EMB  32
#define MPAIR 294528  // N*(N-1)/2
#define EPS  1e-5f
#define NT   48       // NN/16 tile count

// ---------------- scratch (device globals, no allocation) ----------------
__device__ int   g_idx[2][NN][KNB];
__device__ float g_e1[2][NN][EO];
__device__ float g_x[2][NN][XW];
__device__ float g_scale[FEAT];
__device__ float g_shift[FEAT];
__device__ __align__(16) float g_A[2][NN][EMB];
__device__ __align__(16) float g_B[2][NN][EMB];

__device__ __forceinline__ float lrelu(float x) { return fmaxf(x, 0.01f * x); }

// ---- packed f32x2 helpers (sm_103a) ----
__device__ __forceinline__ unsigned long long pk2(float lo, float hi) {
    unsigned long long r;
    asm("mov.b64 %0, {%1,%2};" : "=l"(r) : "f"(lo), "f"(hi));
    return r;
}
__device__ __forceinline__ void upk2(float& lo, float& hi, unsigned long long p) {
    asm("mov.b64 {%0,%1}, %2;" : "=f"(lo), "=f"(hi) : "l"(p));
}
__device__ __forceinline__ unsigned long long fma2(unsigned long long a,
                                                   unsigned long long b,
                                                   unsigned long long c) {
    unsigned long long d;
    asm("fma.rn.f32x2 %0, %1, %2, %3;" : "=l"(d) : "l"(a), "l"(b), "l"(c));
    return d;
}
__device__ __forceinline__ unsigned long long mul2(unsigned long long a,
                                                   unsigned long long b) {
    unsigned long long d;
    asm("mul.rn.f32x2 %0, %1, %2;" : "=l"(d) : "l"(a), "l"(b));
    return d;
}
// packed lrelu: 0.505*x + 0.495*|x|
__device__ __forceinline__ unsigned long long lrelu2(unsigned long long x,
                                                     unsigned long long c1,
                                                     unsigned long long c2) {
    unsigned long long ax = x & 0x7FFFFFFF7FFFFFFFull;
    return fma2(x, c1, mul2(ax, c2));
}

// ---------------- 1) KNN: 8 warps/block, coords staged in shared ----------------
__global__ void __launch_bounds__(256) knn_kernel(const float* __restrict__ feat0,
                                                  const float* __restrict__ feat1) {
    __shared__ float4 sc[NN];
    int g = blockIdx.y;
    int tid = threadIdx.x, wid = tid >> 5, lane = tid & 31;
    const float* feat = g ? feat1 : feat0;
    for (int t = tid; t < NN; t += 256)
        sc[t] = *(const float4*)(feat + t * IN);
    __syncthreads();

    int node = blockIdx.x * 8 + wid;
    float4 ci = sc[node];
    float dloc[NN / 32];
#pragma unroll
    for (int t = 0; t < NN / 32; t++) {
        float4 cj = sc[lane + t * 32];
        dloc[t] = fabsf(ci.x - cj.x) + fabsf(ci.y - cj.y) +
                  fabsf(ci.z - cj.z) + fabsf(ci.w - cj.w);
    }
    for (int r = 0; r < KNB; r++) {
        float best = CUDART_INF_F;
        int bt = 0;
#pragma unroll
        for (int t = 0; t < NN / 32; t++)
            if (dloc[t] < best) { best = dloc[t]; bt = t; }
        int bj = lane + bt * 32;
        unsigned long long key =
            (((unsigned long long)__float_as_uint(best)) << 32) | (unsigned)bj;
#pragma unroll
        for (int off = 16; off; off >>= 1) {
            unsigned long long other = __shfl_xor_sync(0xffffffffu, key, off);
            if (other < key) key = other;
        }
        int wj = (int)(key & 0xffffffffu);
        if (lane == (wj & 31)) dloc[wj >> 5] = CUDART_INF_F;
        if (lane == 0) g_idx[g][node][r] = wj;
    }
}

// ---------------- 2) EdgeConv1: 8 warps/block, 2 nodes per warp ----------------
__global__ void __launch_bounds__(256) ec1_kernel(
        const float* __restrict__ feat0, const float* __restrict__ feat1,
        const float* __restrict__ w1, const float* __restrict__ b1,
        const float* __restrict__ w2, const float* __restrict__ b2) {
    __shared__ float sh[16][KNB][IN];
    __shared__ float s1[16][EO];
    int g = blockIdx.y;
    int wid = threadIdx.x >> 5, lane = threadIdx.x & 31;
    int n0 = blockIdx.x * 16 + wid * 2;
    const float* feat = g ? feat1 : feat0;

#pragma unroll
    for (int nn = 0; nn < 2; nn++) {
        int node = n0 + nn;
        for (int t = lane; t < KNB * IN; t += 32) {
            int k = t / IN, f = t - k * IN;
            sh[wid * 2 + nn][k][f] = feat[g_idx[g][node][k] * IN + f];
        }
    }
    __syncwarp();

    float pa = b1[lane], pb = pa;
    const float (*sa)[IN] = sh[wid * 2];
    const float (*sb)[IN] = sh[wid * 2 + 1];
    for (int f = 0; f < IN; f++) {
#pragma unroll
        for (int k = 0; k < KNB; k++) {
            float w = w1[(f * KNB + k) * EO + lane];
            pa = fmaf(sa[k][f], w, pa);
            pb = fmaf(sb[k][f], w, pb);
        }
    }
    s1[wid * 2][lane]     = lrelu(pa);
    s1[wid * 2 + 1][lane] = lrelu(pb);
    __syncwarp();

    float ha = b2[lane], hb = ha;
#pragma unroll
    for (int k = 0; k < EO; k++) {
        float w = w2[k * EO + lane];
        ha = fmaf(s1[wid * 2][k], w, ha);
        hb = fmaf(s1[wid * 2 + 1][k], w, hb);
    }
    g_e1[g][n0][lane]     = lrelu(ha);
    g_e1[g][n0 + 1][lane] = lrelu(hb);
}

// ---------------- 3) EdgeConv2 + assemble x = [feat|e1|e2] ----------------
__global__ void __launch_bounds__(256) ec2_kernel(
        const float* __restrict__ feat0, const float* __restrict__ feat1,
        const float* __restrict__ w1, const float* __restrict__ b1,
        const float* __restrict__ w2, const float* __restrict__ b2) {
    __shared__ float sh[16][KNB][EO];
    __shared__ float s1[16][EO];
    int g = blockIdx.y;
    int wid = threadIdx.x >> 5, lane = threadIdx.x & 31;
    int n0 = blockIdx.x * 16 + wid * 2;

#pragma unroll
    for (int nn = 0; nn < 2; nn++) {
        int node = n0 + nn;
        for (int t = lane; t < KNB * EO; t += 32) {
            int k = t >> 5, f = t & 31;
            sh[wid * 2 + nn][k][f] = g_e1[g][g_idx[g][node][k]][f];
        }
    }
    __syncwarp();

    float pa = b1[lane], pb = pa;
    const float (*sa)[EO] = sh[wid * 2];
    const float (*sb)[EO] = sh[wid * 2 + 1];
    for (int f = 0; f < EO; f++) {
#pragma unroll
        for (int k = 0; k < KNB; k++) {
            float w = w1[(f * KNB + k) * EO + lane];
            pa = fmaf(sa[k][f], w, pa);
            pb = fmaf(sb[k][f], w, pb);
        }
    }
    s1[wid * 2][lane]     = lrelu(pa);
    s1[wid * 2 + 1][lane] = lrelu(pb);
    __syncwarp();

    float ha = b2[lane], hb = ha;
#pragma unroll
    for (int k = 0; k < EO; k++) {
        float w = w2[k * EO + lane];
        ha = fmaf(s1[wid * 2][k], w, ha);
        hb = fmaf(s1[wid * 2 + 1][k], w, hb);
    }
    const float* feat = g ? feat1 : feat0;
#pragma unroll
    for (int nn = 0; nn < 2; nn++) {
        int node = n0 + nn;
        float* xp = g_x[g][node];
        for (int f = lane; f < IN; f += 32) xp[f] = feat[node * IN + f];
        xp[IN + lane]      = g_e1[g][node][lane];
        xp[IN + EO + lane] = lrelu(nn == 0 ? ha : hb);
    }
}

// ---------------- 4) BN stats: warp per feature, fully unrolled for MLP ----------------
__global__ void __launch_bounds__(128) bn_kernel(const float* __restrict__ bn_g,
                                                 const float* __restrict__ bn_b) {
    int warp = (blockIdx.x * 128 + threadIdx.x) >> 5;
    int lane = threadIdx.x & 31;
    if (warp >= XW) return;
    int f = warp;

    float s1 = 0.f, s2 = 0.f, q1 = 0.f, q2 = 0.f;
#pragma unroll
    for (int t = 0; t < NN / 32; t++) {
        int i = lane + t * 32;
        float wa = (float)(NN - 1 - i);
        float wb = (float)i;
        float v0 = g_x[0][i][f];
        float v1 = g_x[1][i][f];
        s1 = fmaf(wa, v0, s1); s1 = fmaf(wa, v1, s1);
        s2 = fmaf(wb, v0, s2); s2 = fmaf(wb, v1, s2);
        q1 = fmaf(wa * v0, v0, q1); q1 = fmaf(wa * v1, v1, q1);
        q2 = fmaf(wb * v0, v0, q2); q2 = fmaf(wb * v1, v1, q2);
    }
#pragma unroll
    for (int off = 16; off; off >>= 1) {
        s1 += __shfl_xor_sync(0xffffffffu, s1, off);
        s2 += __shfl_xor_sync(0xffffffffu, s2, off);
        q1 += __shfl_xor_sync(0xffffffffu, q1, off);
        q2 += __shfl_xor_sync(0xffffffffu, q2, off);
    }
    if (lane == 0) {
        float inv = 1.0f / (2.0f * (float)MPAIR);
        float mu1 = s1 * inv, var1 = fmaf(-mu1, mu1, q1 * inv);
        float mu2 = s2 * inv, var2 = fmaf(-mu2, mu2, q2 * inv);
        float sc1 = bn_g[f]      * rsqrtf(var1 + EPS);
        float sc2 = bn_g[XW + f] * rsqrtf(var2 + EPS);
        g_scale[f]      = sc1;
        g_scale[XW + f] = sc2;
        g_shift[f]      = bn_b[f]      - mu1 * sc1;
        g_shift[XW + f] = bn_b[XW + f] - mu2 * sc2;
    }
}

// ---------------- 5) per-node A, B (lin1 split + BN folded) ----------------
__global__ void __launch_bounds__(256) ab_kernel(const float* __restrict__ lin1_w,
                                                 const float* __restrict__ lin1_b) {
    int g = blockIdx.y;
    int wid = threadIdx.x >> 5, lane = threadIdx.x & 31;
    int node = blockIdx.x * 8 + wid;

    float be = lin1_b[lane];
    for (int ff = 0; ff < FEAT; ff++)
        be = fmaf(g_shift[ff], lin1_w[ff * EMB + lane], be);

    const float* x = g_x[g][node];
    float a = be, b = 0.f;
    for (int f = 0; f < XW; f++) {
        float xv = x[f];
        float sa = xv * g_scale[f];
        float sb = xv * g_scale[XW + f];
        a = fmaf(sa, lin1_w[f * EMB + lane], a);
        b = fmaf(sb, lin1_w[(XW + f) * EMB + lane], b);
    }
    g_A[g][node][lane] = a;
    g_B[g][node][lane] = b;
}

// ---------------- 6) pair kernel: 16x16 tile, 2 pairs/thread ----------------
// h2[n] = lrelu(b2[n] + sum_k W2[k][n] * h1[k]) with n packed in f32x2 lanes:
// acc[m] holds {s_2m, s_2m+1}; no horizontal reduction per n.
__global__ void __launch_bounds__(128) pair_kernel(
        const float* __restrict__ w2, const float* __restrict__ b2,
        const float* __restrict__ w3, const float* __restrict__ b3,
        float* __restrict__ out) {
    __shared__ float sA[16][33];
    __shared__ float sB[16][33];
    __shared__ __align__(16) float sW2[EMB * EMB];   // raw copy, read as u64 pairs
    __shared__ unsigned long long sW3a[16], sW3b[16], sB2[16];
    __shared__ float b3s[2];

    int t = threadIdx.x;
    int g = blockIdx.y;

    // tile decode: upper-triangle (a<=b) over 48x48 tiles
    int T = blockIdx.x, a = 0;
    while (T >= NT - a) { T -= NT - a; a++; }
    int b = a + T;
    int i0 = a * 16, j0 = b * 16;

    // stage A/B tiles (coalesced: 16 consecutive rows = 512 contiguous floats)
    {
        float4 av = ((const float4*)g_A[g][i0])[t];
        int r = t >> 3, c = (t & 7) * 4;
        sA[r][c] = av.x; sA[r][c + 1] = av.y; sA[r][c + 2] = av.z; sA[r][c + 3] = av.w;
        float4 bv = ((const float4*)g_B[g][j0])[t];
        sB[r][c] = bv.x; sB[r][c + 1] = bv.y; sB[r][c + 2] = bv.z; sB[r][c + 3] = bv.w;
    }
    ((float4*)sW2)[t]       = ((const float4*)w2)[t];
    ((float4*)sW2)[t + 128] = ((const float4*)w2)[t + 128];
    if (t < 16) {
        sB2[t]  = ((const unsigned long long*)b2)[t];
        sW3a[t] = pk2(w3[4 * t],     w3[4 * t + 2]);
        sW3b[t] = pk2(w3[4 * t + 1], w3[4 * t + 3]);
    }
    if (t < 2) b3s[t] = b3[t];
    __syncthreads();

    int ty = t >> 3, tx = t & 7;
    int i = i0 + ty;
    int j = j0 + 2 * tx;

    unsigned long long acc0[16], acc1[16];
#pragma unroll
    for (int m = 0; m < 16; m++) { acc0[m] = sB2[m]; acc1[m] = sB2[m]; }

    const ulonglong2* wv = (const ulonglong2*)sW2;
#pragma unroll 8
    for (int k = 0; k < EMB; k++) {
        float av  = sA[ty][k];
        float h0s = lrelu(av + sB[2 * tx][k]);
        float h1s = lrelu(av + sB[2 * tx + 1][k]);
        unsigned long long h0 = pk2(h0s, h0s);
        unsigned long long h1 = pk2(h1s, h1s);
#pragma unroll
        for (int mm = 0; mm < 8; mm++) {
            ulonglong2 w = wv[k * 8 + mm];
            acc0[2 * mm]     = fma2(h0, w.x, acc0[2 * mm]);
            acc0[2 * mm + 1] = fma2(h0, w.y, acc0[2 * mm + 1]);
            acc1[2 * mm]     = fma2(h1, w.x, acc1[2 * mm]);
            acc1[2 * mm + 1] = fma2(h1, w.y, acc1[2 * mm + 1]);
        }
    }

    const unsigned long long c1 = pk2(0.505f, 0.505f);
    const unsigned long long c2 = pk2(0.495f, 0.495f);

    unsigned long long p00 = 0, p01 = 0, p10 = 0, p11 = 0;
#pragma unroll
    for (int m = 0; m < 16; m++) {
        unsigned long long h2a = lrelu2(acc0[m], c1, c2);
        unsigned long long h2b = lrelu2(acc1[m], c1, c2);
        unsigned long long wa = sW3a[m], wb = sW3b[m];
        p00 = fma2(h2a, wa, p00);
        p01 = fma2(h2a, wb, p01);
        p10 = fma2(h2b, wa, p10);
        p11 = fma2(h2b, wb, p11);
    }
    float lo, hi;
    upk2(lo, hi, p00); float r00 = lo + hi + b3s[0];
    upk2(lo, hi, p01); float r01 = lo + hi + b3s[1];
    upk2(lo, hi, p10); float r10 = lo + hi + b3s[0];
    upk2(lo, hi, p11); float r11 = lo + hi + b3s[1];

    float2* outp = (float2*)out + (long long)g * MPAIR;
    int base = i * (2 * NN - 1 - i) / 2 - i - 1;   // q = base + j
    if (j > i)     outp[base + j]     = make_float2(r00, r01);
    if (j + 1 > i) outp[base + j + 1] = make_float2(r10, r11);
}

// ---------------- launch ----------------
extern "C" void kernel_launch(void* const* d_in, const int* in_sizes, int n_in,
                              void* d_out, int out_size) {
    const float* feat0  = (const float*)d_in[0];
    const float* feat1  = (const float*)d_in[1];
    const float* ec1_w1 = (const float*)d_in[2];
    const float* ec1_b1 = (const float*)d_in[3];
    const float* ec1_w2 = (const float*)d_in[4];
    const float* ec1_b2 = (const float*)d_in[5];
    const float* ec2_w1 = (const float*)d_in[6];
    const float* ec2_b1 = (const float*)d_in[7];
    const float* ec2_w2 = (const float*)d_in[8];
    const float* ec2_b2 = (const float*)d_in[9];
    const float* bn_g   = (const float*)d_in[10];
    const float* bn_b   = (const float*)d_in[11];
    const float* lin1_w = (const float*)d_in[12];
    const float* lin1_b = (const float*)d_in[13];
    const float* lin2_w = (const float*)d_in[14];
    const float* lin2_b = (const float*)d_in[15];
    const float* lin3_w = (const float*)d_in[16];
    const float* lin3_b = (const float*)d_in[17];
    float* out = (float*)d_out;

    knn_kernel<<<dim3(NN / 8, 2), 256>>>(feat0, feat1);
    ec1_kernel<<<dim3(NN / 16, 2), 256>>>(feat0, feat1, ec1_w1, ec1_b1, ec1_w2, ec1_b2);
    ec2_kernel<<<dim3(NN / 16, 2), 256>>>(feat0, feat1, ec2_w1, ec2_b1, ec2_w2, ec2_b2);
    bn_kernel<<<(XW * 32 + 127) / 128, 128>>>(bn_g, bn_b);
    ab_kernel<<<dim3(NN / 8, 2), 256>>>(lin1_w, lin1_b);
    pair_kernel<<<dim3(NT * (NT + 1) / 2, 2), 128>>>(lin2_w, lin2_b, lin3_w, lin3_b, out);
}

// round 12
// speedup vs baseline: 1.5624x; 1.1244x over previous
#include <cuda_runtime.h>
#include <cuda_bf16.h>
#include <math_constants.h>
#include <cstdint>

#define NN   768
#define IN   68
#define KNB  8
#define EO   32
#define FEAT 264      // IN*2 + EO*4
#define XW   132      // per-node feature width: IN + EO + EO
#define EMB  32
#define MPAIR 294528  // N*(N-1)/2
#define EPS  1e-5f
#define NT   48       // NN/16 tile count

// ---------------- scratch (device globals, no allocation) ----------------
__device__ int   g_idx[2][NN][KNB];
__device__ float g_e1[2][NN][EO];
__device__ float g_x[2][NN][XW];
__device__ float g_accum[4][XW];     // s1, s2, q1, q2
__device__ __align__(16) float g_A[2][NN][EMB];
__device__ __align__(16) float g_B[2][NN][EMB];

__device__ __forceinline__ float lrelu(float x) { return fmaxf(x, 0.01f * x); }

// ---- packed f32x2 helpers (sm_103a) ----
__device__ __forceinline__ unsigned long long pk2(float lo, float hi) {
    unsigned long long r;
    asm("mov.b64 %0, {%1,%2};" : "=l"(r) : "f"(lo), "f"(hi));
    return r;
}
__device__ __forceinline__ void upk2(float& lo, float& hi, unsigned long long p) {
    asm("mov.b64 {%0,%1}, %2;" : "=f"(lo), "=f"(hi) : "l"(p));
}
__device__ __forceinline__ unsigned long long fma2(unsigned long long a,
                                                   unsigned long long b,
                                                   unsigned long long c) {
    unsigned long long d;
    asm("fma.rn.f32x2 %0, %1, %2, %3;" : "=l"(d) : "l"(a), "l"(b), "l"(c));
    return d;
}
__device__ __forceinline__ unsigned long long mul2(unsigned long long a,
                                                   unsigned long long b) {
    unsigned long long d;
    asm("mul.rn.f32x2 %0, %1, %2;" : "=l"(d) : "l"(a), "l"(b));
    return d;
}
// packed lrelu: 0.505*x + 0.495*|x|
__device__ __forceinline__ unsigned long long lrelu2(unsigned long long x,
                                                     unsigned long long c1,
                                                     unsigned long long c2) {
    unsigned long long ax = x & 0x7FFFFFFF7FFFFFFFull;
    return fma2(x, c1, mul2(ax, c2));
}

// ======== 1) fused KNN + EdgeConv1: 16 nodes/block, 8 warps ========
__global__ void __launch_bounds__(256) knn_ec1_kernel(
        const float* __restrict__ feat0, const float* __restrict__ feat1,
        const float* __restrict__ w1, const float* __restrict__ b1,
        const float* __restrict__ w2, const float* __restrict__ b2) {
    // phase union: knn uses float4 sc[NN] (12.3KB); ec1 uses sh[16][8][68] (34.8KB)
    __shared__ __align__(16) unsigned char smem_u[16 * KNB * IN * 4];
    __shared__ float s1[16][EO];
    __shared__ int   sidx[16][KNB];

    int g = blockIdx.y;
    int tid = threadIdx.x, wid = tid >> 5, lane = tid & 31;
    const float* feat = g ? feat1 : feat0;

    if (blockIdx.x == 0 && g == 0) {
        float* acc = (float*)g_accum;
        for (int t = tid; t < 4 * XW; t += 256) acc[t] = 0.f;
    }

    // ---- phase A: KNN (2 nodes per warp, sequential) ----
    float4* sc = (float4*)smem_u;
    for (int t = tid; t < NN; t += 256)
        sc[t] = *(const float4*)(feat + t * IN);
    __syncthreads();

    int nbase = blockIdx.x * 16 + wid * 2;
#pragma unroll
    for (int nn = 0; nn < 2; nn++) {
        int node = nbase + nn;
        float4 ci = sc[node];
        float dloc[NN / 32];
#pragma unroll
        for (int t = 0; t < NN / 32; t++) {
            float4 cj = sc[lane + t * 32];
            dloc[t] = fabsf(ci.x - cj.x) + fabsf(ci.y - cj.y) +
                      fabsf(ci.z - cj.z) + fabsf(ci.w - cj.w);
        }
        for (int r = 0; r < KNB; r++) {
            float best = CUDART_INF_F;
            int bt = 0;
#pragma unroll
            for (int t = 0; t < NN / 32; t++)
                if (dloc[t] < best) { best = dloc[t]; bt = t; }
            int bj = lane + bt * 32;
            unsigned long long key =
                (((unsigned long long)__float_as_uint(best)) << 32) | (unsigned)bj;
#pragma unroll
            for (int off = 16; off; off >>= 1) {
                unsigned long long other = __shfl_xor_sync(0xffffffffu, key, off);
                if (other < key) key = other;
            }
            int wj = (int)(key & 0xffffffffu);
            if (lane == (wj & 31)) dloc[wj >> 5] = CUDART_INF_F;
            if (lane == 0) {
                sidx[wid * 2 + nn][r] = wj;
                g_idx[g][node][r] = wj;   // for ec2
            }
        }
    }
    __syncthreads();   // sc dead; sidx complete

    // ---- phase B: EdgeConv1 (2 nodes per warp) ----
    float (*sh)[KNB][IN] = (float (*)[KNB][IN])smem_u;
#pragma unroll
    for (int nn = 0; nn < 2; nn++) {
        int slot = wid * 2 + nn;
        for (int t = lane; t < KNB * IN; t += 32) {
            int k = t / IN, f = t - k * IN;
            sh[slot][k][f] = feat[sidx[slot][k] * IN + f];
        }
    }
    __syncwarp();

    float pa = b1[lane], pb = pa;
    const float (*sa)[IN] = sh[wid * 2];
    const float (*sb)[IN] = sh[wid * 2 + 1];
    for (int f = 0; f < IN; f++) {
#pragma unroll
        for (int k = 0; k < KNB; k++) {
            float w = w1[(f * KNB + k) * EO + lane];
            pa = fmaf(sa[k][f], w, pa);
            pb = fmaf(sb[k][f], w, pb);
        }
    }
    s1[wid * 2][lane]     = lrelu(pa);
    s1[wid * 2 + 1][lane] = lrelu(pb);
    __syncwarp();

    float ha = b2[lane], hb = ha;
#pragma unroll
    for (int k = 0; k < EO; k++) {
        float w = w2[k * EO + lane];
        ha = fmaf(s1[wid * 2][k], w, ha);
        hb = fmaf(s1[wid * 2 + 1][k], w, hb);
    }
    g_e1[g][nbase][lane]     = lrelu(ha);
    g_e1[g][nbase + 1][lane] = lrelu(hb);
}

// ------- 2) EdgeConv2 + assemble x + bn partial accumulation -------
__global__ void __launch_bounds__(256) ec2_kernel(
        const float* __restrict__ feat0, const float* __restrict__ feat1,
        const float* __restrict__ w1, const float* __restrict__ b1,
        const float* __restrict__ w2, const float* __restrict__ b2) {
    __shared__ float sh[16][KNB][EO];
    __shared__ float s1[16][EO];
    __shared__ float pacc[4][XW];
    int g = blockIdx.y;
    int tid = threadIdx.x;
    int wid = tid >> 5, lane = tid & 31;
    int n0 = blockIdx.x * 16 + wid * 2;

    for (int t = tid; t < 4 * XW; t += 256) ((float*)pacc)[t] = 0.f;

#pragma unroll
    for (int nn = 0; nn < 2; nn++) {
        int node = n0 + nn;
        for (int t = lane; t < KNB * EO; t += 32) {
            int k = t >> 5, f = t & 31;
            sh[wid * 2 + nn][k][f] = g_e1[g][g_idx[g][node][k]][f];
        }
    }
    __syncwarp();

    float pa = b1[lane], pb = pa;
    const float (*sa)[EO] = sh[wid * 2];
    const float (*sb)[EO] = sh[wid * 2 + 1];
    for (int f = 0; f < EO; f++) {
#pragma unroll
        for (int k = 0; k < KNB; k++) {
            float w = w1[(f * KNB + k) * EO + lane];
            pa = fmaf(sa[k][f], w, pa);
            pb = fmaf(sb[k][f], w, pb);
        }
    }
    s1[wid * 2][lane]     = lrelu(pa);
    s1[wid * 2 + 1][lane] = lrelu(pb);
    __syncwarp();

    float ha = b2[lane], hb = ha;
#pragma unroll
    for (int k = 0; k < EO; k++) {
        float w = w2[k * EO + lane];
        ha = fmaf(s1[wid * 2][k], w, ha);
        hb = fmaf(s1[wid * 2 + 1][k], w, hb);
    }
    const float* feat = g ? feat1 : feat0;
#pragma unroll
    for (int nn = 0; nn < 2; nn++) {
        int node = n0 + nn;
        float* xp = g_x[g][node];
        for (int f = lane; f < IN; f += 32) xp[f] = feat[node * IN + f];
        xp[IN + lane]      = g_e1[g][node][lane];
        xp[IN + EO + lane] = lrelu(nn == 0 ? ha : hb);
    }
    __syncthreads();   // pacc zero + x writes visible

    // bn partials for this block's 16 nodes (each warp: its own 2 nodes)
#pragma unroll
    for (int nn = 0; nn < 2; nn++) {
        int node = n0 + nn;
        float wa = (float)(NN - 1 - node);
        float wb = (float)node;
        for (int f = lane; f < XW; f += 32) {
            float v = g_x[g][node][f];
            atomicAdd(&pacc[0][f], wa * v);
            atomicAdd(&pacc[1][f], wb * v);
            atomicAdd(&pacc[2][f], wa * v * v);
            atomicAdd(&pacc[3][f], wb * v * v);
        }
    }
    __syncthreads();
    for (int t = tid; t < 4 * XW; t += 256)
        atomicAdd(&((float*)g_accum)[t], ((float*)pacc)[t]);
}

// ------- 3) per-node A, B (bn finalize in-block + lin1 split + BN fold) -------
__global__ void __launch_bounds__(256) ab_kernel(const float* __restrict__ lin1_w,
                                                 const float* __restrict__ lin1_b,
                                                 const float* __restrict__ bn_g,
                                                 const float* __restrict__ bn_b) {
    __shared__ float sscale[FEAT], sshift[FEAT];
    int g = blockIdx.y;
    int tid = threadIdx.x;
    int wid = tid >> 5, lane = tid & 31;
    int node = blockIdx.x * 8 + wid;

    if (tid < XW) {
        int f = tid;
        float inv = 1.0f / (2.0f * (float)MPAIR);
        float s1 = g_accum[0][f], s2 = g_accum[1][f];
        float q1 = g_accum[2][f], q2 = g_accum[3][f];
        float mu1 = s1 * inv, var1 = fmaf(-mu1, mu1, q1 * inv);
        float mu2 = s2 * inv, var2 = fmaf(-mu2, mu2, q2 * inv);
        float sc1 = bn_g[f]      * rsqrtf(var1 + EPS);
        float sc2 = bn_g[XW + f] * rsqrtf(var2 + EPS);
        sscale[f]      = sc1;
        sscale[XW + f] = sc2;
        sshift[f]      = bn_b[f]      - mu1 * sc1;
        sshift[XW + f] = bn_b[XW + f] - mu2 * sc2;
    }
    __syncthreads();

    float be = lin1_b[lane];
    for (int ff = 0; ff < FEAT; ff++)
        be = fmaf(sshift[ff], lin1_w[ff * EMB + lane], be);

    const float* x = g_x[g][node];
    float a = be, b = 0.f;
    for (int f = 0; f < XW; f++) {
        float xv = x[f];
        float sa = xv * sscale[f];
        float sb = xv * sscale[XW + f];
        a = fmaf(sa, lin1_w[f * EMB + lane], a);
        b = fmaf(sb, lin1_w[(XW + f) * EMB + lane], b);
    }
    g_A[g][node][lane] = a;
    g_B[g][node][lane] = b;
}

// ---------------- 4) pair kernel: 16x16 tile, 2 pairs/thread ----------------
// h2[n] = lrelu(b2[n] + sum_k W2[k][n] * h1[k]) with n packed in f32x2 lanes.
__global__ void __launch_bounds__(128) pair_kernel(
        const float* __restrict__ w2, const float* __restrict__ b2,
        const float* __restrict__ w3, const float* __restrict__ b3,
        float* __restrict__ out) {
    __shared__ float sA[16][33];
    __shared__ float sBT[EMB][16];    // transposed: sBT[k][j] — LDS.64 per thread
    __shared__ __align__(16) float sW2[EMB * EMB];   // raw copy, read as u64 pairs
    __shared__ unsigned long long sW3a[16], sW3b[16], sB2[16];
    __shared__ float b3s[2];

    int t = threadIdx.x;
    int g = blockIdx.y;

    // tile decode: upper-triangle (a<=b) over 48x48 tiles
    int T = blockIdx.x, a = 0;
    while (T >= NT - a) { T -= NT - a; a++; }
    int b = a + T;
    int i0 = a * 16, j0 = b * 16;

    // stage A tile (row-major) and B tile (transposed)
    {
        float4 av = ((const float4*)g_A[g][i0])[t];
        int r = t >> 3, c = (t & 7) * 4;
        sA[r][c] = av.x; sA[r][c + 1] = av.y; sA[r][c + 2] = av.z; sA[r][c + 3] = av.w;
        float4 bv = ((const float4*)g_B[g][j0])[t];
        sBT[c][r] = bv.x; sBT[c + 1][r] = bv.y; sBT[c + 2][r] = bv.z; sBT[c + 3][r] = bv.w;
    }
    ((float4*)sW2)[t]       = ((const float4*)w2)[t];
    ((float4*)sW2)[t + 128] = ((const float4*)w2)[t + 128];
    if (t < 16) {
        sB2[t]  = ((const unsigned long long*)b2)[t];
        sW3a[t] = pk2(w3[4 * t],     w3[4 * t + 2]);
        sW3b[t] = pk2(w3[4 * t + 1], w3[4 * t + 3]);
    }
    if (t < 2) b3s[t] = b3[t];
    __syncthreads();

    int ty = t >> 3, tx = t & 7;
    int i = i0 + ty;
    int j = j0 + 2 * tx;

    unsigned long long acc0[16], acc1[16];
#pragma unroll
    for (int m = 0; m < 16; m++) { acc0[m] = sB2[m]; acc1[m] = sB2[m]; }

    const ulonglong2* wv = (const ulonglong2*)sW2;
#pragma unroll 8
    for (int k = 0; k < EMB; k++) {
        float av = sA[ty][k];
        float2 bv = *(const float2*)&sBT[k][2 * tx];
        float h0s = lrelu(av + bv.x);
        float h1s = lrelu(av + bv.y);
        unsigned long long h0 = pk2(h0s, h0s);
        unsigned long long h1 = pk2(h1s, h1s);
#pragma unroll
        for (int mm = 0; mm < 8; mm++) {
            ulonglong2 w = wv[k * 8 + mm];
            acc0[2 * mm]     = fma2(h0, w.x, acc0[2 * mm]);
            acc0[2 * mm + 1] = fma2(h0, w.y, acc0[2 * mm + 1]);
            acc1[2 * mm]     = fma2(h1, w.x, acc1[2 * mm]);
            acc1[2 * mm + 1] = fma2(h1, w.y, acc1[2 * mm + 1]);
        }
    }

    const unsigned long long c1 = pk2(0.505f, 0.505f);
    const unsigned long long c2 = pk2(0.495f, 0.495f);

    unsigned long long p00 = 0, p01 = 0, p10 = 0, p11 = 0;
#pragma unroll
    for (int m = 0; m < 16; m++) {
        unsigned long long h2a = lrelu2(acc0[m], c1, c2);
        unsigned long long h2b = lrelu2(acc1[m], c1, c2);
        unsigned long long wa = sW3a[m], wb = sW3b[m];
        p00 = fma2(h2a, wa, p00);
        p01 = fma2(h2a, wb, p01);
        p10 = fma2(h2b, wa, p10);
        p11 = fma2(h2b, wb, p11);
    }
    float lo, hi;
    upk2(lo, hi, p00); float r00 = lo + hi + b3s[0];
    upk2(lo, hi, p01); float r01 = lo + hi + b3s[1];
    upk2(lo, hi, p10); float r10 = lo + hi + b3s[0];
    upk2(lo, hi, p11); float r11 = lo + hi + b3s[1];

    float2* outp = (float2*)out + (long long)g * MPAIR;
    int base = i * (2 * NN - 1 - i) / 2 - i - 1;   // q = base + j
    if (j > i)     outp[base + j]     = make_float2(r00, r01);
    if (j + 1 > i) outp[base + j + 1] = make_float2(r10, r11);
}

// ---------------- launch ----------------
extern "C" void kernel_launch(void* const* d_in, const int* in_sizes, int n_in,
                              void* d_out, int out_size) {
    const float* feat0  = (const float*)d_in[0];
    const float* feat1  = (const float*)d_in[1];
    const float* ec1_w1 = (const float*)d_in[2];
    const float* ec1_b1 = (const float*)d_in[3];
    const float* ec1_w2 = (const float*)d_in[4];
    const float* ec1_b2 = (const float*)d_in[5];
    const float* ec2_w1 = (const float*)d_in[6];
    const float* ec2_b1 = (const float*)d_in[7];
    const float* ec2_w2 = (const float*)d_in[8];
    const float* ec2_b2 = (const float*)d_in[9];
    const float* bn_g   = (const float*)d_in[10];
    const float* bn_b   = (const float*)d_in[11];
    const float* lin1_w = (const float*)d_in[12];
    const float* lin1_b = (const float*)d_in[13];
    const float* lin2_w = (const float*)d_in[14];
    const float* lin2_b = (const float*)d_in[15];
    const float* lin3_w = (const float*)d_in[16];
    const float* lin3_b = (const float*)d_in[17];
    float* out = (float*)d_out;

    knn_ec1_kernel<<<dim3(NN / 16, 2), 256>>>(feat0, feat1, ec1_w1, ec1_b1, ec1_w2, ec1_b2);
    ec2_kernel<<<dim3(NN / 16, 2), 256>>>(feat0, feat1, ec2_w1, ec2_b1, ec2_w2, ec2_b2);
    ab_kernel<<<dim3(NN / 8, 2), 256>>>(lin1_w, lin1_b, bn_g, bn_b);
    pair_kernel<<<dim3(NT * (NT + 1) / 2, 2), 128>>>(lin2_w, lin2_b, lin3_w, lin3_b, out);
}

// round 13
// speedup vs baseline: 1.7774x; 1.1376x over previous
#include <cuda_runtime.h>
#include <cuda_bf16.h>
#include <math_constants.h>
#include <cstdint>

#define NN   768
#define IN   68
#define KNB  8
#define EO   32
#define FEAT 264      // IN*2 + EO*4
#define XW   132      // per-node feature width: IN + EO + EO
#define EMB  32
#define MPAIR 294528  // N*(N-1)/2
#define EPS  1e-5f
#define NT   48       // NN/16 tile count

// ---------------- scratch (device globals, no allocation) ----------------
__device__ int   g_idx[2][NN][KNB];
__device__ float g_e1[2][NN][EO];
__device__ float g_x[2][NN][XW];
__device__ float g_accum[4][XW];     // s1, s2, q1, q2
__device__ __align__(16) float g_A[2][NN][EMB];
__device__ __align__(16) float g_B[2][NN][EMB];

__device__ __forceinline__ float lrelu(float x) { return fmaxf(x, 0.01f * x); }

// ---- packed f32x2 helpers (sm_103a) ----
__device__ __forceinline__ unsigned long long pk2(float lo, float hi) {
    unsigned long long r;
    asm("mov.b64 %0, {%1,%2};" : "=l"(r) : "f"(lo), "f"(hi));
    return r;
}
__device__ __forceinline__ void upk2(float& lo, float& hi, unsigned long long p) {
    asm("mov.b64 {%0,%1}, %2;" : "=f"(lo), "=f"(hi) : "l"(p));
}
__device__ __forceinline__ unsigned long long fma2(unsigned long long a,
                                                   unsigned long long b,
                                                   unsigned long long c) {
    unsigned long long d;
    asm("fma.rn.f32x2 %0, %1, %2, %3;" : "=l"(d) : "l"(a), "l"(b), "l"(c));
    return d;
}
__device__ __forceinline__ unsigned long long mul2(unsigned long long a,
                                                   unsigned long long b) {
    unsigned long long d;
    asm("mul.rn.f32x2 %0, %1, %2;" : "=l"(d) : "l"(a), "l"(b));
    return d;
}
// packed lrelu: 0.505*x + 0.495*|x|
__device__ __forceinline__ unsigned long long lrelu2(unsigned long long x,
                                                     unsigned long long c1,
                                                     unsigned long long c2) {
    unsigned long long ax = x & 0x7FFFFFFF7FFFFFFFull;
    return fma2(x, c1, mul2(ax, c2));
}

// ======== 1) fused KNN + EdgeConv1: 4 nodes/block (1 per warp) ========
__global__ void __launch_bounds__(128) knn_ec1_kernel(
        const float* __restrict__ feat0, const float* __restrict__ feat1,
        const float* __restrict__ w1, const float* __restrict__ b1,
        const float* __restrict__ w2, const float* __restrict__ b2) {
    // union: knn coords float4[768] (12.3KB) vs ec1 gather sh[4][8][68] (8.7KB)
    __shared__ __align__(16) unsigned char smem_u[NN * 16];
    __shared__ float s1[4][EO];
    __shared__ int   sidx[4][KNB];

    int g = blockIdx.y;
    int tid = threadIdx.x, wid = tid >> 5, lane = tid & 31;
    const float* feat = g ? feat1 : feat0;
    int node = blockIdx.x * 4 + wid;

    if (blockIdx.x == 0 && g == 0) {
        float* acc = (float*)g_accum;
        for (int t = tid; t < 4 * XW; t += 128) acc[t] = 0.f;
    }

    // ---- phase A: KNN (1 node per warp) ----
    float4* sc = (float4*)smem_u;
    for (int t = tid; t < NN; t += 128)
        sc[t] = *(const float4*)(feat + t * IN);
    __syncthreads();

    {
        float4 ci = sc[node];
        float dloc[NN / 32];
#pragma unroll
        for (int t = 0; t < NN / 32; t++) {
            float4 cj = sc[lane + t * 32];
            dloc[t] = fabsf(ci.x - cj.x) + fabsf(ci.y - cj.y) +
                      fabsf(ci.z - cj.z) + fabsf(ci.w - cj.w);
        }
        for (int r = 0; r < KNB; r++) {
            float best = CUDART_INF_F;
            int bt = 0;
#pragma unroll
            for (int t = 0; t < NN / 32; t++)
                if (dloc[t] < best) { best = dloc[t]; bt = t; }
            int bj = lane + bt * 32;
            unsigned long long key =
                (((unsigned long long)__float_as_uint(best)) << 32) | (unsigned)bj;
#pragma unroll
            for (int off = 16; off; off >>= 1) {
                unsigned long long other = __shfl_xor_sync(0xffffffffu, key, off);
                if (other < key) key = other;
            }
            int wj = (int)(key & 0xffffffffu);
            if (lane == (wj & 31)) dloc[wj >> 5] = CUDART_INF_F;
            if (lane == 0) {
                sidx[wid][r] = wj;
                g_idx[g][node][r] = wj;
            }
        }
    }
    __syncthreads();   // sc dead

    // ---- phase B: EdgeConv1 (1 node per warp, dual accumulators) ----
    float (*sh)[KNB][IN] = (float (*)[KNB][IN])smem_u;
    for (int t = lane; t < KNB * IN; t += 32) {
        int k = t / IN, f = t - k * IN;
        sh[wid][k][f] = feat[sidx[wid][k] * IN + f];
    }
    __syncwarp();

    float p0 = b1[lane], p1 = 0.f;
    const float (*sa)[IN] = sh[wid];
    for (int f = 0; f < IN; f += 2) {
#pragma unroll
        for (int k = 0; k < KNB; k++) {
            p0 = fmaf(sa[k][f],     w1[(f * KNB + k) * EO + lane],       p0);
            p1 = fmaf(sa[k][f + 1], w1[((f + 1) * KNB + k) * EO + lane], p1);
        }
    }
    s1[wid][lane] = lrelu(p0 + p1);
    __syncwarp();

    float h = b2[lane];
#pragma unroll
    for (int k = 0; k < EO; k++)
        h = fmaf(s1[wid][k], w2[k * EO + lane], h);
    g_e1[g][node][lane] = lrelu(h);
}

// ------- 2) EdgeConv2 (smem weights) + assemble x + bn partials -------
__global__ void __launch_bounds__(128) ec2_kernel(
        const float* __restrict__ feat0, const float* __restrict__ feat1,
        const float* __restrict__ w1, const float* __restrict__ b1,
        const float* __restrict__ w2, const float* __restrict__ b2) {
    __shared__ float sw1[EO * KNB * EO];   // 32 KB
    __shared__ float sw2[EO * EO];         // 4 KB
    __shared__ float sh[4][KNB][EO];       // 4 KB
    __shared__ float s1[4][EO];
    __shared__ float pacc[4][XW];          // 2.1 KB
    int g = blockIdx.y;
    int tid = threadIdx.x;
    int wid = tid >> 5, lane = tid & 31;
    int node = blockIdx.x * 4 + wid;

    for (int t = tid; t < EO * KNB * EO / 4; t += 128)
        ((float4*)sw1)[t] = ((const float4*)w1)[t];
    for (int t = tid; t < EO * EO / 4; t += 128)
        ((float4*)sw2)[t] = ((const float4*)w2)[t];
    for (int t = tid; t < 4 * XW; t += 128) ((float*)pacc)[t] = 0.f;

    for (int t = lane; t < KNB * EO; t += 32) {
        int k = t >> 5, f = t & 31;
        sh[wid][k][f] = g_e1[g][g_idx[g][node][k]][f];
    }
    __syncthreads();

    float p0 = b1[lane], p1 = 0.f;
    const float (*sa)[EO] = sh[wid];
    for (int f = 0; f < EO; f += 2) {
#pragma unroll
        for (int k = 0; k < KNB; k++) {
            p0 = fmaf(sa[k][f],     sw1[(f * KNB + k) * EO + lane],       p0);
            p1 = fmaf(sa[k][f + 1], sw1[((f + 1) * KNB + k) * EO + lane], p1);
        }
    }
    s1[wid][lane] = lrelu(p0 + p1);
    __syncwarp();

    float h = b2[lane];
#pragma unroll
    for (int k = 0; k < EO; k++)
        h = fmaf(s1[wid][k], sw2[k * EO + lane], h);

    const float* feat = g ? feat1 : feat0;
    float* xp = g_x[g][node];
    for (int f = lane; f < IN; f += 32) xp[f] = feat[node * IN + f];
    xp[IN + lane]      = g_e1[g][node][lane];
    xp[IN + EO + lane] = lrelu(h);
    __syncthreads();

    // bn partials (each warp its node)
    {
        float wa = (float)(NN - 1 - node);
        float wb = (float)node;
        for (int f = lane; f < XW; f += 32) {
            float v = g_x[g][node][f];
            atomicAdd(&pacc[0][f], wa * v);
            atomicAdd(&pacc[1][f], wb * v);
            atomicAdd(&pacc[2][f], wa * v * v);
            atomicAdd(&pacc[3][f], wb * v * v);
        }
    }
    __syncthreads();
    for (int t = tid; t < 4 * XW; t += 128)
        atomicAdd(&((float*)g_accum)[t], ((float*)pacc)[t]);
}

// ------- 3) per-node A, B: smem lin1_w, block-shared be -------
__global__ void __launch_bounds__(128) ab_kernel(const float* __restrict__ lin1_w,
                                                 const float* __restrict__ lin1_b,
                                                 const float* __restrict__ bn_g,
                                                 const float* __restrict__ bn_b) {
    __shared__ float sw[FEAT * EMB];       // 33 KB
    __shared__ float sscale[FEAT], sshift[FEAT];
    __shared__ float sbe[4][EMB];
    __shared__ float sx[4][XW];
    int g = blockIdx.y;
    int tid = threadIdx.x;
    int wid = tid >> 5, lane = tid & 31;
    int node = blockIdx.x * 4 + wid;

    for (int t = tid; t < FEAT * EMB / 4; t += 128)
        ((float4*)sw)[t] = ((const float4*)lin1_w)[t];
    for (int f = tid; f < XW; f += 128) {
        float inv = 1.0f / (2.0f * (float)MPAIR);
        float s1 = g_accum[0][f], s2 = g_accum[1][f];
        float q1 = g_accum[2][f], q2 = g_accum[3][f];
        float mu1 = s1 * inv, var1 = fmaf(-mu1, mu1, q1 * inv);
        float mu2 = s2 * inv, var2 = fmaf(-mu2, mu2, q2 * inv);
        float sc1 = bn_g[f]      * rsqrtf(var1 + EPS);
        float sc2 = bn_g[XW + f] * rsqrtf(var2 + EPS);
        sscale[f]      = sc1;
        sscale[XW + f] = sc2;
        sshift[f]      = bn_b[f]      - mu1 * sc1;
        sshift[XW + f] = bn_b[XW + f] - mu2 * sc2;
    }
    // stage this warp's node features
    {
        const float* x = g_x[g][node];
        for (int f = lane; f < XW; f += 32) sx[wid][f] = x[f];
    }
    __syncthreads();

    // be partial: warp w covers ff ≡ w (mod 4)
    {
        float p = 0.f;
        for (int ff = wid; ff < FEAT; ff += 4)
            p = fmaf(sshift[ff], sw[ff * EMB + lane], p);
        sbe[wid][lane] = p;
    }
    __syncthreads();

    float a = lin1_b[lane] + sbe[0][lane] + sbe[1][lane] + sbe[2][lane] + sbe[3][lane];
    float b = 0.f;
    for (int f = 0; f < XW; f++) {
        float xv = sx[wid][f];
        a = fmaf(xv * sscale[f],      sw[f * EMB + lane],        a);
        b = fmaf(xv * sscale[XW + f], sw[(XW + f) * EMB + lane], b);
    }
    g_A[g][node][lane] = a;
    g_B[g][node][lane] = b;
}

// ---------------- 4) pair kernel: 16x16 tile, both graphs per block ----------------
__global__ void __launch_bounds__(128) pair_kernel(
        const float* __restrict__ w2, const float* __restrict__ b2,
        const float* __restrict__ w3, const float* __restrict__ b3,
        float* __restrict__ out) {
    __shared__ float sA[16][33];
    __shared__ float sBT[EMB][16];
    __shared__ __align__(16) float sW2[EMB * EMB];
    __shared__ unsigned long long sW3a[16], sW3b[16], sB2[16];
    __shared__ float b3s[2];

    int t = threadIdx.x;

    // tile decode: upper-triangle (a<=b) over 48x48 tiles
    int T = blockIdx.x, a = 0;
    while (T >= NT - a) { T -= NT - a; a++; }
    int b = a + T;
    int i0 = a * 16, j0 = b * 16;

    ((float4*)sW2)[t]       = ((const float4*)w2)[t];
    ((float4*)sW2)[t + 128] = ((const float4*)w2)[t + 128];
    if (t < 16) {
        sB2[t]  = ((const unsigned long long*)b2)[t];
        sW3a[t] = pk2(w3[4 * t],     w3[4 * t + 2]);
        sW3b[t] = pk2(w3[4 * t + 1], w3[4 * t + 3]);
    }
    if (t < 2) b3s[t] = b3[t];

    int ty = t >> 3, tx = t & 7;
    int i = i0 + ty;
    int j = j0 + 2 * tx;
    int base = i * (2 * NN - 1 - i) / 2 - i - 1;   // q = base + j

    const unsigned long long c1 = pk2(0.505f, 0.505f);
    const unsigned long long c2 = pk2(0.495f, 0.495f);
    const ulonglong2* wv = (const ulonglong2*)sW2;

    for (int g = 0; g < 2; g++) {
        if (g) __syncthreads();    // protect sA/sBT reuse
        {
            float4 av = ((const float4*)g_A[g][i0])[t];
            int r = t >> 3, c = (t & 7) * 4;
            sA[r][c] = av.x; sA[r][c + 1] = av.y; sA[r][c + 2] = av.z; sA[r][c + 3] = av.w;
            float4 bv = ((const float4*)g_B[g][j0])[t];
            sBT[c][r] = bv.x; sBT[c + 1][r] = bv.y; sBT[c + 2][r] = bv.z; sBT[c + 3][r] = bv.w;
        }
        __syncthreads();

        unsigned long long acc0[16], acc1[16];
#pragma unroll
        for (int m = 0; m < 16; m++) { acc0[m] = sB2[m]; acc1[m] = sB2[m]; }

#pragma unroll 8
        for (int k = 0; k < EMB; k++) {
            float av = sA[ty][k];
            float2 bv = *(const float2*)&sBT[k][2 * tx];
            float h0s = lrelu(av + bv.x);
            float h1s = lrelu(av + bv.y);
            unsigned long long h0 = pk2(h0s, h0s);
            unsigned long long h1 = pk2(h1s, h1s);
#pragma unroll
            for (int mm = 0; mm < 8; mm++) {
                ulonglong2 w = wv[k * 8 + mm];
                acc0[2 * mm]     = fma2(h0, w.x, acc0[2 * mm]);
                acc0[2 * mm + 1] = fma2(h0, w.y, acc0[2 * mm + 1]);
                acc1[2 * mm]     = fma2(h1, w.x, acc1[2 * mm]);
                acc1[2 * mm + 1] = fma2(h1, w.y, acc1[2 * mm + 1]);
            }
        }

        unsigned long long p00 = 0, p01 = 0, p10 = 0, p11 = 0;
#pragma unroll
        for (int m = 0; m < 16; m++) {
            unsigned long long h2a = lrelu2(acc0[m], c1, c2);
            unsigned long long h2b = lrelu2(acc1[m], c1, c2);
            unsigned long long wa = sW3a[m], wb = sW3b[m];
            p00 = fma2(h2a, wa, p00);
            p01 = fma2(h2a, wb, p01);
            p10 = fma2(h2b, wa, p10);
            p11 = fma2(h2b, wb, p11);
        }
        float lo, hi;
        upk2(lo, hi, p00); float r00 = lo + hi + b3s[0];
        upk2(lo, hi, p01); float r01 = lo + hi + b3s[1];
        upk2(lo, hi, p10); float r10 = lo + hi + b3s[0];
        upk2(lo, hi, p11); float r11 = lo + hi + b3s[1];

        float2* outp = (float2*)out + (long long)g * MPAIR;
        if (j > i)     outp[base + j]     = make_float2(r00, r01);
        if (j + 1 > i) outp[base + j + 1] = make_float2(r10, r11);
    }
}

// ---------------- launch ----------------
extern "C" void kernel_launch(void* const* d_in, const int* in_sizes, int n_in,
                              void* d_out, int out_size) {
    const float* feat0  = (const float*)d_in[0];
    const float* feat1  = (const float*)d_in[1];
    const float* ec1_w1 = (const float*)d_in[2];
    const float* ec1_b1 = (const float*)d_in[3];
    const float* ec1_w2 = (const float*)d_in[4];
    const float* ec1_b2 = (const float*)d_in[5];
    const float* ec2_w1 = (const float*)d_in[6];
    const float* ec2_b1 = (const float*)d_in[7];
    const float* ec2_w2 = (const float*)d_in[8];
    const float* ec2_b2 = (const float*)d_in[9];
    const float* bn_g   = (const float*)d_in[10];
    const float* bn_b   = (const float*)d_in[11];
    const float* lin1_w = (const float*)d_in[12];
    const float* lin1_b = (const float*)d_in[13];
    const float* lin2_w = (const float*)d_in[14];
    const float* lin2_b = (const float*)d_in[15];
    const float* lin3_w = (const float*)d_in[16];
    const float* lin3_b = (const float*)d_in[17];
    float* out = (float*)d_out;

    knn_ec1_kernel<<<dim3(NN / 4, 2), 128>>>(feat0, feat1, ec1_w1, ec1_b1, ec1_w2, ec1_b2);
    ec2_kernel<<<dim3(NN / 4, 2), 128>>>(feat0, feat1, ec2_w1, ec2_b1, ec2_w2, ec2_b2);
    ab_kernel<<<dim3(NN / 4, 2), 128>>>(lin1_w, lin1_b, bn_g, bn_b);
    pair_kernel<<<NT * (NT + 1) / 2, 128>>>(lin2_w, lin2_b, lin3_w, lin3_b, out);
}